// round 2
// baseline (speedup 1.0000x reference)
#include <cuda_runtime.h>
#include <cuda_bf16.h>
#include <math.h>

#define B_   2
#define S_   2048
#define H_   2048
#define NH_  16
#define NKV_ 4
#define DH_  128
#define I_   8192
#define M_   (B_ * S_)          // 4096 tokens
#define GROUPS_ (NH_ / NKV_)    // 4
#define EPS_ 1e-6f

// ---------------- scratch (device globals; no runtime allocation) ----------------
__device__ float g_xnorm[M_ * H_];
__device__ float g_q[M_ * NH_ * DH_];
__device__ float g_k[M_ * NKV_ * DH_];
__device__ float g_v[M_ * NKV_ * DH_];
__device__ float g_attn[M_ * NH_ * DH_];
__device__ float g_h1[M_ * H_];
__device__ float g_x2[M_ * H_];
__device__ float g_gate[(size_t)M_ * I_];
__device__ float g_up[(size_t)M_ * I_];

// ---------------- RMSNorm over rows of length Hdim ----------------
__global__ void rmsnorm_kernel(const float* __restrict__ x, const float* __restrict__ w,
                               float* __restrict__ y, int Hdim) {
    int row = blockIdx.x;
    const float4* xr = (const float4*)(x + (size_t)row * Hdim);
    float4* yr = (float4*)(y + (size_t)row * Hdim);
    const float4* wv = (const float4*)w;
    int n4 = Hdim >> 2;

    float ss = 0.f;
    for (int i = threadIdx.x; i < n4; i += blockDim.x) {
        float4 v = xr[i];
        ss += v.x * v.x + v.y * v.y + v.z * v.z + v.w * v.w;
    }
    // block reduce (256 threads = 8 warps)
    __shared__ float wsum[8];
    for (int o = 16; o > 0; o >>= 1) ss += __shfl_xor_sync(0xffffffffu, ss, o);
    int warp = threadIdx.x >> 5;
    if ((threadIdx.x & 31) == 0) wsum[warp] = ss;
    __syncthreads();
    __shared__ float s_inv;
    if (threadIdx.x == 0) {
        float t = 0.f;
        #pragma unroll
        for (int i = 0; i < 8; i++) t += wsum[i];
        s_inv = rsqrtf(t / (float)Hdim + EPS_);
    }
    __syncthreads();
    float inv = s_inv;
    for (int i = threadIdx.x; i < n4; i += blockDim.x) {
        float4 v = xr[i];
        float4 ww = wv[i];
        float4 o;
        o.x = v.x * inv * ww.x; o.y = v.y * inv * ww.y;
        o.z = v.z * inv * ww.z; o.w = v.w * inv * ww.w;
        yr[i] = o;
    }
}

// ---------------- per-(token,head) RMSNorm + RoPE, DH=128, 128 threads ----------------
__global__ void qknorm_rope_kernel(float* __restrict__ x, const float* __restrict__ w,
                                   const float* __restrict__ cosp, const float* __restrict__ sinp,
                                   int nheads) {
    int idx = blockIdx.x;
    int head = idx % nheads;
    int token = idx / nheads;
    float* p = x + ((size_t)token * nheads + head) * DH_;
    int d = threadIdx.x;

    float v = p[d];
    float ss = v * v;
    for (int o = 16; o > 0; o >>= 1) ss += __shfl_xor_sync(0xffffffffu, ss, o);
    __shared__ float wsum[4];
    int warp = d >> 5;
    if ((d & 31) == 0) wsum[warp] = ss;
    __syncthreads();
    float tot = wsum[0] + wsum[1] + wsum[2] + wsum[3];
    float inv = rsqrtf(tot / (float)DH_ + EPS_);
    float vn = v * inv * w[d];

    __shared__ float sh[DH_];
    sh[d] = vn;
    __syncthreads();
    float other = (d < 64) ? -sh[d + 64] : sh[d - 64];
    float c = cosp[(size_t)token * DH_ + d];
    float s = sinp[(size_t)token * DH_ + d];
    p[d] = vn * c + other * s;
}

// ---------------- SGEMM: C[M,N] = A[M,K] @ B[K,N] (+ Res), fp32 ----------------
// 128x128 block tile, BK=16, 256 threads, 8x8 per-thread microtile
__global__ __launch_bounds__(256) void sgemm128(const float* __restrict__ A,
                                                const float* __restrict__ Bm,
                                                const float* __restrict__ Res,
                                                float* __restrict__ C,
                                                int M, int N, int K) {
    __shared__ float As[16][132];   // transposed A tile, padded
    __shared__ float Bs[16][128];

    int tid = threadIdx.x;
    int tx = tid & 15, ty = tid >> 4;
    int rowBase = blockIdx.y * 128;
    int colBase = blockIdx.x * 128;

    float acc[8][8];
    #pragma unroll
    for (int i = 0; i < 8; i++)
        #pragma unroll
        for (int j = 0; j < 8; j++) acc[i][j] = 0.f;

    for (int k0 = 0; k0 < K; k0 += 16) {
        // load A tile 128x16 (transposed into As)
        #pragma unroll
        for (int it = 0; it < 2; it++) {
            int slot = tid + it * 256;
            int r = slot >> 2;
            int c4 = (slot & 3) * 4;
            float4 v = *(const float4*)(A + (size_t)(rowBase + r) * K + k0 + c4);
            As[c4 + 0][r] = v.x;
            As[c4 + 1][r] = v.y;
            As[c4 + 2][r] = v.z;
            As[c4 + 3][r] = v.w;
        }
        // load B tile 16x128
        #pragma unroll
        for (int it = 0; it < 2; it++) {
            int slot = tid + it * 256;
            int r = slot >> 5;
            int c4 = (slot & 31) * 4;
            *(float4*)&Bs[r][c4] = *(const float4*)(Bm + (size_t)(k0 + r) * N + colBase + c4);
        }
        __syncthreads();

        #pragma unroll
        for (int k = 0; k < 16; k++) {
            float a[8], b[8];
            #pragma unroll
            for (int i = 0; i < 8; i++) a[i] = As[k][ty * 8 + i];
            #pragma unroll
            for (int j = 0; j < 8; j++) b[j] = Bs[k][tx * 8 + j];
            #pragma unroll
            for (int i = 0; i < 8; i++)
                #pragma unroll
                for (int j = 0; j < 8; j++) acc[i][j] = fmaf(a[i], b[j], acc[i][j]);
        }
        __syncthreads();
    }

    #pragma unroll
    for (int i = 0; i < 8; i++) {
        int row = rowBase + ty * 8 + i;
        size_t base = (size_t)row * N + colBase + tx * 8;
        if (Res != nullptr) {
            #pragma unroll
            for (int j = 0; j < 8; j++) C[base + j] = acc[i][j] + Res[base + j];
        } else {
            #pragma unroll
            for (int j = 0; j < 8; j++) C[base + j] = acc[i][j];
        }
    }
}

// ---------------- Flash attention, fp32, full (non-causal) softmax ----------------
// grid: (S/64, NH, B), 256 threads (16x16), 64 q-rows x 64 k-rows tiles
#define ATTN_SMEM_FLOATS (2 * 64 * 129 + 64 * 128 + 64 * 65)
__global__ __launch_bounds__(256) void attn_kernel(const float* __restrict__ q,
                                                   const float* __restrict__ k,
                                                   const float* __restrict__ v,
                                                   float* __restrict__ o) {
    extern __shared__ float sm[];
    float* Qs = sm;                 // 64 x 129
    float* Ks = Qs + 64 * 129;      // 64 x 129
    float* Vs = Ks + 64 * 129;      // 64 x 128
    float* Ps = Vs + 64 * 128;      // 64 x 65

    int qb = blockIdx.x, h = blockIdx.y, b = blockIdx.z;
    int kvh = h / GROUPS_;
    int tid = threadIdx.x;
    int tx = tid & 15, ty = tid >> 4;

    const float scale = 0.08838834764831845f;  // 1/sqrt(128)

    // load & scale Q tile (64 x 128)
    for (int s = tid; s < 64 * 32; s += 256) {
        int r = s >> 5;
        int c4 = (s & 31) * 4;
        int srow = qb * 64 + r;
        float4 qv = *(const float4*)(q + (((size_t)(b * S_ + srow)) * NH_ + h) * DH_ + c4);
        Qs[r * 129 + c4 + 0] = qv.x * scale;
        Qs[r * 129 + c4 + 1] = qv.y * scale;
        Qs[r * 129 + c4 + 2] = qv.z * scale;
        Qs[r * 129 + c4 + 3] = qv.w * scale;
    }

    float m[4], l[4], acc[4][8];
    #pragma unroll
    for (int i = 0; i < 4; i++) {
        m[i] = -INFINITY; l[i] = 0.f;
        #pragma unroll
        for (int dd = 0; dd < 8; dd++) acc[i][dd] = 0.f;
    }

    for (int kt = 0; kt < S_ / 64; kt++) {
        __syncthreads();
        // load K,V tiles
        for (int s = tid; s < 64 * 32; s += 256) {
            int r = s >> 5;
            int c4 = (s & 31) * 4;
            int j = kt * 64 + r;
            size_t gbase = (((size_t)(b * S_ + j)) * NKV_ + kvh) * DH_ + c4;
            float4 kv = *(const float4*)(k + gbase);
            Ks[r * 129 + c4 + 0] = kv.x;
            Ks[r * 129 + c4 + 1] = kv.y;
            Ks[r * 129 + c4 + 2] = kv.z;
            Ks[r * 129 + c4 + 3] = kv.w;
            *(float4*)&Vs[r * 128 + c4] = *(const float4*)(v + gbase);
        }
        __syncthreads();

        // scores 4x4 per thread: rows ty*4+i, cols tx*4+j
        float sc[4][4];
        #pragma unroll
        for (int i = 0; i < 4; i++)
            #pragma unroll
            for (int j = 0; j < 4; j++) sc[i][j] = 0.f;
        for (int d = 0; d < DH_; d++) {
            float qr[4], kr[4];
            #pragma unroll
            for (int i = 0; i < 4; i++) qr[i] = Qs[(ty * 4 + i) * 129 + d];
            #pragma unroll
            for (int j = 0; j < 4; j++) kr[j] = Ks[(tx * 4 + j) * 129 + d];
            #pragma unroll
            for (int i = 0; i < 4; i++)
                #pragma unroll
                for (int j = 0; j < 4; j++) sc[i][j] = fmaf(qr[i], kr[j], sc[i][j]);
        }

        // online softmax per row
        #pragma unroll
        for (int i = 0; i < 4; i++) {
            float tmax = sc[i][0];
            #pragma unroll
            for (int j = 1; j < 4; j++) tmax = fmaxf(tmax, sc[i][j]);
            #pragma unroll
            for (int off = 1; off < 16; off <<= 1)
                tmax = fmaxf(tmax, __shfl_xor_sync(0xffffffffu, tmax, off));
            float newm = fmaxf(m[i], tmax);
            float psum = 0.f;
            #pragma unroll
            for (int j = 0; j < 4; j++) {
                float p = __expf(sc[i][j] - newm);
                sc[i][j] = p;
                psum += p;
            }
            #pragma unroll
            for (int off = 1; off < 16; off <<= 1)
                psum += __shfl_xor_sync(0xffffffffu, psum, off);
            float alpha = __expf(m[i] - newm);
            l[i] = l[i] * alpha + psum;
            m[i] = newm;
            #pragma unroll
            for (int dd = 0; dd < 8; dd++) acc[i][dd] *= alpha;
            #pragma unroll
            for (int j = 0; j < 4; j++) Ps[(ty * 4 + i) * 65 + tx * 4 + j] = sc[i][j];
        }
        __syncthreads();

        // O += P @ V : rows ty*4+i, cols tx*8+dd
        for (int j = 0; j < 64; j++) {
            float vv[8];
            #pragma unroll
            for (int dd = 0; dd < 8; dd++) vv[dd] = Vs[j * 128 + tx * 8 + dd];
            #pragma unroll
            for (int i = 0; i < 4; i++) {
                float p = Ps[(ty * 4 + i) * 65 + j];
                #pragma unroll
                for (int dd = 0; dd < 8; dd++) acc[i][dd] = fmaf(p, vv[dd], acc[i][dd]);
            }
        }
    }

    // write out: layout (b, s, h, d)
    #pragma unroll
    for (int i = 0; i < 4; i++) {
        int srow = qb * 64 + ty * 4 + i;
        float invl = 1.f / l[i];
        size_t base = (((size_t)(b * S_ + srow)) * NH_ + h) * DH_ + tx * 8;
        #pragma unroll
        for (int dd = 0; dd < 8; dd++) o[base + dd] = acc[i][dd] * invl;
    }
}

// ---------------- silu(gate) * up, in-place into gate ----------------
__global__ void silu_mul_kernel(float* __restrict__ g, const float* __restrict__ u, size_t n4) {
    size_t i = (size_t)blockIdx.x * blockDim.x + threadIdx.x;
    if (i >= n4) return;
    float4 gv = ((const float4*)g)[i];
    float4 uv = ((const float4*)u)[i];
    float4 o;
    o.x = gv.x / (1.f + __expf(-gv.x)) * uv.x;
    o.y = gv.y / (1.f + __expf(-gv.y)) * uv.y;
    o.z = gv.z / (1.f + __expf(-gv.z)) * uv.z;
    o.w = gv.w / (1.f + __expf(-gv.w)) * uv.w;
    ((float4*)g)[i] = o;
}

// ---------------- launch ----------------
extern "C" void kernel_launch(void* const* d_in, const int* in_sizes, int n_in,
                              void* d_out, int out_size) {
    const float* hidden = (const float*)d_in[0];
    const float* cosp   = (const float*)d_in[1];
    const float* sinp   = (const float*)d_in[2];
    const float* wq     = (const float*)d_in[3];
    const float* wk     = (const float*)d_in[4];
    const float* wv     = (const float*)d_in[5];
    const float* wo     = (const float*)d_in[6];
    const float* qnw    = (const float*)d_in[7];
    const float* knw    = (const float*)d_in[8];
    const float* anw    = (const float*)d_in[9];
    const float* mnw    = (const float*)d_in[10];
    const float* wgate  = (const float*)d_in[11];
    const float* wup    = (const float*)d_in[12];
    const float* wdown  = (const float*)d_in[13];
    float* out = (float*)d_out;

    float *xnorm, *q, *k, *v, *attn, *h1, *x2, *gate, *up;
    cudaGetSymbolAddress((void**)&xnorm, g_xnorm);
    cudaGetSymbolAddress((void**)&q, g_q);
    cudaGetSymbolAddress((void**)&k, g_k);
    cudaGetSymbolAddress((void**)&v, g_v);
    cudaGetSymbolAddress((void**)&attn, g_attn);
    cudaGetSymbolAddress((void**)&h1, g_h1);
    cudaGetSymbolAddress((void**)&x2, g_x2);
    cudaGetSymbolAddress((void**)&gate, g_gate);
    cudaGetSymbolAddress((void**)&up, g_up);

    const int attn_smem = ATTN_SMEM_FLOATS * sizeof(float);
    cudaFuncSetAttribute(attn_kernel, cudaFuncAttributeMaxDynamicSharedMemorySize, attn_smem);

    // 1) attn rmsnorm
    rmsnorm_kernel<<<M_, 256>>>(hidden, anw, xnorm, H_);

    // 2) QKV projections
    sgemm128<<<dim3(H_ / 128, M_ / 128), 256>>>(xnorm, wq, nullptr, q, M_, NH_ * DH_, H_);
    sgemm128<<<dim3((NKV_ * DH_) / 128, M_ / 128), 256>>>(xnorm, wk, nullptr, k, M_, NKV_ * DH_, H_);
    sgemm128<<<dim3((NKV_ * DH_) / 128, M_ / 128), 256>>>(xnorm, wv, nullptr, v, M_, NKV_ * DH_, H_);

    // 3) q/k norm + rope
    qknorm_rope_kernel<<<M_ * NH_, DH_>>>(q, qnw, cosp, sinp, NH_);
    qknorm_rope_kernel<<<M_ * NKV_, DH_>>>(k, knw, cosp, sinp, NKV_);

    // 4) attention
    attn_kernel<<<dim3(S_ / 64, NH_, B_), 256, attn_smem>>>(q, k, v, attn);

    // 5) O projection + residual
    sgemm128<<<dim3(H_ / 128, M_ / 128), 256>>>(attn, wo, hidden, h1, M_, H_, NH_ * DH_);

    // 6) mlp rmsnorm
    rmsnorm_kernel<<<M_, 256>>>(h1, mnw, x2, H_);

    // 7) gate/up projections
    sgemm128<<<dim3(I_ / 128, M_ / 128), 256>>>(x2, wgate, nullptr, gate, M_, I_, H_);
    sgemm128<<<dim3(I_ / 128, M_ / 128), 256>>>(x2, wup, nullptr, up, M_, I_, H_);

    // 8) silu * up
    {
        size_t n4 = ((size_t)M_ * I_) / 4;
        int blocks = (int)((n4 + 255) / 256);
        silu_mul_kernel<<<blocks, 256>>>(gate, up, n4);
    }

    // 9) down projection + residual -> output
    sgemm128<<<dim3(H_ / 128, M_ / 128), 256>>>(gate, wdown, h1, out, M_, H_, I_);
}

// round 3
// speedup vs baseline: 2.0061x; 2.0061x over previous
#include <cuda_runtime.h>
#include <cuda_bf16.h>
#include <math.h>
#include <stdint.h>

#define B_   2
#define S_   2048
#define H_   2048
#define NH_  16
#define NKV_ 4
#define DH_  128
#define I_   8192
#define M_   (B_ * S_)          // 4096 tokens
#define GROUPS_ (NH_ / NKV_)    // 4
#define EPS_ 1e-6f

#define QKV_N_ 3072             // 2048 q + 512 k + 512 v
#define GU_N_  16384            // 8192 gate + 8192 up

// ---------------- scratch (device globals; no runtime allocation) ----------------
__device__ float g_xnorm[(size_t)M_ * H_];
__device__ float g_qkv[(size_t)M_ * QKV_N_];
__device__ float g_attn[(size_t)M_ * H_];
__device__ float g_h1[(size_t)M_ * H_];
__device__ float g_x2[(size_t)M_ * H_];
__device__ float g_gu[(size_t)M_ * GU_N_];
__device__ float g_act[(size_t)M_ * I_];
// tf32-converted weights
__device__ float w_qkv[(size_t)H_ * QKV_N_];
__device__ float w_o[(size_t)H_ * H_];
__device__ float w_gu[(size_t)H_ * GU_N_];
__device__ float w_dn[(size_t)I_ * H_];

// ---------------- helpers ----------------
__device__ __forceinline__ float to_tf32(float x) {
    uint32_t r;
    asm("cvt.rna.tf32.f32 %0, %1;" : "=r"(r) : "f"(x));
    return __uint_as_float(r);
}

__device__ __forceinline__ uint32_t smem_u32(const void* p) {
    return (uint32_t)__cvta_generic_to_shared(p);
}

__device__ __forceinline__ void cp_async16(uint32_t dst, const void* src) {
    asm volatile("cp.async.cg.shared.global [%0], [%1], 16;\n" :: "r"(dst), "l"(src));
}
__device__ __forceinline__ void cp_commit() { asm volatile("cp.async.commit_group;\n"); }
__device__ __forceinline__ void cp_wait0()  { asm volatile("cp.async.wait_group 0;\n"); }

__device__ __forceinline__ void mma_tf32(float* d, const uint32_t* a, uint32_t b0, uint32_t b1) {
    asm volatile(
        "mma.sync.aligned.m16n8k8.row.col.f32.tf32.tf32.f32 "
        "{%0,%1,%2,%3}, {%4,%5,%6,%7}, {%8,%9}, {%0,%1,%2,%3};\n"
        : "+f"(d[0]), "+f"(d[1]), "+f"(d[2]), "+f"(d[3])
        : "r"(a[0]), "r"(a[1]), "r"(a[2]), "r"(a[3]), "r"(b0), "r"(b1));
}

// ---------------- weight convert (fp32 -> tf32) with column placement ----------------
// src: [rows][ncols4*4] row-major; dst row stride dstStride4 float4s, column offset colOff4.
__global__ void cvt2d_kernel(const float* __restrict__ src, float* __restrict__ dst,
                             int ncols4, int dstStride4, int colOff4, long total4) {
    long i = (long)blockIdx.x * blockDim.x + threadIdx.x;
    if (i >= total4) return;
    long r = i / ncols4;
    int c = (int)(i - r * ncols4);
    float4 v = ((const float4*)src)[i];
    v.x = to_tf32(v.x); v.y = to_tf32(v.y); v.z = to_tf32(v.z); v.w = to_tf32(v.w);
    ((float4*)dst)[r * (long)dstStride4 + colOff4 + c] = v;
}

// ---------------- RMSNorm over rows of length Hdim, output tf32 ----------------
__global__ void rmsnorm_kernel(const float* __restrict__ x, const float* __restrict__ w,
                               float* __restrict__ y, int Hdim) {
    int row = blockIdx.x;
    const float4* xr = (const float4*)(x + (size_t)row * Hdim);
    float4* yr = (float4*)(y + (size_t)row * Hdim);
    const float4* wv = (const float4*)w;
    int n4 = Hdim >> 2;

    float ss = 0.f;
    for (int i = threadIdx.x; i < n4; i += blockDim.x) {
        float4 v = xr[i];
        ss += v.x * v.x + v.y * v.y + v.z * v.z + v.w * v.w;
    }
    __shared__ float wsum[8];
    for (int o = 16; o > 0; o >>= 1) ss += __shfl_xor_sync(0xffffffffu, ss, o);
    int warp = threadIdx.x >> 5;
    if ((threadIdx.x & 31) == 0) wsum[warp] = ss;
    __syncthreads();
    __shared__ float s_inv;
    if (threadIdx.x == 0) {
        float t = 0.f;
        #pragma unroll
        for (int i = 0; i < 8; i++) t += wsum[i];
        s_inv = rsqrtf(t / (float)Hdim + EPS_);
    }
    __syncthreads();
    float inv = s_inv;
    for (int i = threadIdx.x; i < n4; i += blockDim.x) {
        float4 v = xr[i];
        float4 ww = wv[i];
        float4 o;
        o.x = to_tf32(v.x * inv * ww.x); o.y = to_tf32(v.y * inv * ww.y);
        o.z = to_tf32(v.z * inv * ww.z); o.w = to_tf32(v.w * inv * ww.w);
        yr[i] = o;
    }
}

// ---------------- per-(token,head) RMSNorm + RoPE, DH=128, 128 threads ----------------
__global__ void qknorm_rope_kernel(float* __restrict__ base, int rowStride,
                                   const float* __restrict__ w,
                                   const float* __restrict__ cosp, const float* __restrict__ sinp,
                                   int nheads) {
    int idx = blockIdx.x;
    int head = idx % nheads;
    int token = idx / nheads;
    float* p = base + (size_t)token * rowStride + head * DH_;
    int d = threadIdx.x;

    float v = p[d];
    float ss = v * v;
    for (int o = 16; o > 0; o >>= 1) ss += __shfl_xor_sync(0xffffffffu, ss, o);
    __shared__ float wsum[4];
    int warp = d >> 5;
    if ((d & 31) == 0) wsum[warp] = ss;
    __syncthreads();
    float tot = wsum[0] + wsum[1] + wsum[2] + wsum[3];
    float inv = rsqrtf(tot / (float)DH_ + EPS_);
    float vn = v * inv * w[d];

    __shared__ float sh[DH_];
    sh[d] = vn;
    __syncthreads();
    float other = (d < 64) ? -sh[d + 64] : sh[d - 64];
    float c = cosp[(size_t)token * DH_ + d];
    float s = sinp[(size_t)token * DH_ + d];
    p[d] = vn * c + other * s;
}

// ---------------- tf32 tensor-core GEMM ----------------
// C[M,N] = A[M,K] @ B[K,N] (+ Res). A,B already tf32-quantized fp32 bit patterns.
// 128x128x32 block tile, 4 warps (128 thr), warp tile 64x64, m16n8k8 tf32 mma,
// 2-stage cp.async pipeline. Requires M%128==0, N%128==0, K%32==0.
#define G_STAGE (128 * 36 + 32 * 136)   // floats per stage: As + Bs

__device__ __forceinline__ void gemm_issue(const float* __restrict__ Abase,
                                           const float* __restrict__ Bm, long N, long colBase,
                                           float* As, float* Bs, int tid, int k0) {
    uint32_t aDst = smem_u32(As + tid * 36);
    const float* aSrc = Abase + k0;
    #pragma unroll
    for (int i = 0; i < 8; i++)
        cp_async16(aDst + i * 16, aSrc + i * 4);
    #pragma unroll
    for (int p = 0; p < 8; p++) {
        int f = tid + p * 128;
        int kr = f >> 5, n4 = f & 31;
        cp_async16(smem_u32(Bs + kr * 136 + n4 * 4),
                   Bm + (long)(k0 + kr) * N + colBase + n4 * 4);
    }
}

__device__ __forceinline__ void gemm_compute(const float* As, const float* Bs,
                                             int wm, int wn, int gid, int tig,
                                             float (&acc)[4][8][4]) {
    #pragma unroll
    for (int kk = 0; kk < 32; kk += 8) {
        uint32_t a[4][4];
        #pragma unroll
        for (int mi = 0; mi < 4; mi++) {
            const float* ap = As + (wm + mi * 16 + gid) * 36;
            a[mi][0] = __float_as_uint(ap[kk + tig]);
            a[mi][1] = __float_as_uint(ap[8 * 36 + kk + tig]);
            a[mi][2] = __float_as_uint(ap[kk + tig + 4]);
            a[mi][3] = __float_as_uint(ap[8 * 36 + kk + tig + 4]);
        }
        #pragma unroll
        for (int ni = 0; ni < 8; ni++) {
            uint32_t b0 = __float_as_uint(Bs[(kk + tig) * 136 + wn + ni * 8 + gid]);
            uint32_t b1 = __float_as_uint(Bs[(kk + tig + 4) * 136 + wn + ni * 8 + gid]);
            #pragma unroll
            for (int mi = 0; mi < 4; mi++)
                mma_tf32(acc[mi][ni], a[mi], b0, b1);
        }
    }
}

__global__ __launch_bounds__(128) void gemm_tf32(const float* __restrict__ A,
                                                 const float* __restrict__ Bm,
                                                 const float* __restrict__ Res,
                                                 float* __restrict__ C,
                                                 int M, int N, int K) {
    extern __shared__ float sm[];
    int tid = threadIdx.x;
    int wid = tid >> 5, lane = tid & 31;
    int gid = lane >> 2, tig = lane & 3;
    int wm = (wid >> 1) * 64, wn = (wid & 1) * 64;
    long rowBase = (long)blockIdx.y * 128;
    long colBase = (long)blockIdx.x * 128;

    float acc[4][8][4] = {};

    const float* Abase = A + (rowBase + tid) * (long)K;
    float* As0 = sm;
    float* Bs0 = sm + 128 * 36;
    float* As1 = sm + G_STAGE;
    float* Bs1 = As1 + 128 * 36;

    int nIter = K / 32;
    gemm_issue(Abase, Bm, N, colBase, As0, Bs0, tid, 0);
    cp_commit();
    cp_wait0();
    __syncthreads();

    for (int it = 0; it < nIter; it++) {
        int cur = it & 1;
        if (it + 1 < nIter) {
            gemm_issue(Abase, Bm, N, colBase, cur ? As0 : As1, cur ? Bs0 : Bs1,
                       tid, (it + 1) * 32);
            cp_commit();
        }
        gemm_compute(cur ? As1 : As0, cur ? Bs1 : Bs0, wm, wn, gid, tig, acc);
        if (it + 1 < nIter) {
            cp_wait0();
            __syncthreads();
        }
    }

    // epilogue
    #pragma unroll
    for (int mi = 0; mi < 4; mi++) {
        #pragma unroll
        for (int ni = 0; ni < 8; ni++) {
            long r0 = rowBase + wm + mi * 16 + gid;
            long c = colBase + wn + ni * 8 + tig * 2;
            float2 v0 = make_float2(acc[mi][ni][0], acc[mi][ni][1]);
            float2 v1 = make_float2(acc[mi][ni][2], acc[mi][ni][3]);
            if (Res != nullptr) {
                float2 r0v = *(const float2*)(Res + r0 * N + c);
                float2 r1v = *(const float2*)(Res + (r0 + 8) * N + c);
                v0.x += r0v.x; v0.y += r0v.y;
                v1.x += r1v.x; v1.y += r1v.y;
            }
            *(float2*)(C + r0 * N + c) = v0;
            *(float2*)(C + (r0 + 8) * N + c) = v1;
        }
    }
}

// ---------------- Flash attention, fp32, reads from fused qkv buffer ----------------
#define ATTN_SMEM_FLOATS (2 * 64 * 129 + 64 * 128 + 64 * 65)
__global__ __launch_bounds__(256) void attn_kernel(const float* __restrict__ qkv,
                                                   float* __restrict__ o) {
    extern __shared__ float sm[];
    float* Qs = sm;                 // 64 x 129
    float* Ks = Qs + 64 * 129;      // 64 x 129
    float* Vs = Ks + 64 * 129;      // 64 x 128
    float* Ps = Vs + 64 * 128;      // 64 x 65

    int qb = blockIdx.x, h = blockIdx.y, b = blockIdx.z;
    int kvh = h / GROUPS_;
    int tid = threadIdx.x;
    int tx = tid & 15, ty = tid >> 4;

    const float scale = 0.08838834764831845f;  // 1/sqrt(128)

    for (int s = tid; s < 64 * 32; s += 256) {
        int r = s >> 5;
        int c4 = (s & 31) * 4;
        int srow = qb * 64 + r;
        float4 qv = *(const float4*)(qkv + (size_t)(b * S_ + srow) * QKV_N_ + h * DH_ + c4);
        Qs[r * 129 + c4 + 0] = qv.x * scale;
        Qs[r * 129 + c4 + 1] = qv.y * scale;
        Qs[r * 129 + c4 + 2] = qv.z * scale;
        Qs[r * 129 + c4 + 3] = qv.w * scale;
    }

    float m[4], l[4], acc[4][8];
    #pragma unroll
    for (int i = 0; i < 4; i++) {
        m[i] = -INFINITY; l[i] = 0.f;
        #pragma unroll
        for (int dd = 0; dd < 8; dd++) acc[i][dd] = 0.f;
    }

    for (int kt = 0; kt < S_ / 64; kt++) {
        __syncthreads();
        for (int s = tid; s < 64 * 32; s += 256) {
            int r = s >> 5;
            int c4 = (s & 31) * 4;
            int j = kt * 64 + r;
            size_t gbase = (size_t)(b * S_ + j) * QKV_N_ + kvh * DH_ + c4;
            float4 kv = *(const float4*)(qkv + 2048 + gbase);
            Ks[r * 129 + c4 + 0] = kv.x;
            Ks[r * 129 + c4 + 1] = kv.y;
            Ks[r * 129 + c4 + 2] = kv.z;
            Ks[r * 129 + c4 + 3] = kv.w;
            *(float4*)&Vs[r * 128 + c4] = *(const float4*)(qkv + 2560 + gbase);
        }
        __syncthreads();

        float sc[4][4];
        #pragma unroll
        for (int i = 0; i < 4; i++)
            #pragma unroll
            for (int j = 0; j < 4; j++) sc[i][j] = 0.f;
        for (int d = 0; d < DH_; d++) {
            float qr[4], kr[4];
            #pragma unroll
            for (int i = 0; i < 4; i++) qr[i] = Qs[(ty * 4 + i) * 129 + d];
            #pragma unroll
            for (int j = 0; j < 4; j++) kr[j] = Ks[(tx * 4 + j) * 129 + d];
            #pragma unroll
            for (int i = 0; i < 4; i++)
                #pragma unroll
                for (int j = 0; j < 4; j++) sc[i][j] = fmaf(qr[i], kr[j], sc[i][j]);
        }

        #pragma unroll
        for (int i = 0; i < 4; i++) {
            float tmax = sc[i][0];
            #pragma unroll
            for (int j = 1; j < 4; j++) tmax = fmaxf(tmax, sc[i][j]);
            #pragma unroll
            for (int off = 1; off < 16; off <<= 1)
                tmax = fmaxf(tmax, __shfl_xor_sync(0xffffffffu, tmax, off));
            float newm = fmaxf(m[i], tmax);
            float psum = 0.f;
            #pragma unroll
            for (int j = 0; j < 4; j++) {
                float p = __expf(sc[i][j] - newm);
                sc[i][j] = p;
                psum += p;
            }
            #pragma unroll
            for (int off = 1; off < 16; off <<= 1)
                psum += __shfl_xor_sync(0xffffffffu, psum, off);
            float alpha = __expf(m[i] - newm);
            l[i] = l[i] * alpha + psum;
            m[i] = newm;
            #pragma unroll
            for (int dd = 0; dd < 8; dd++) acc[i][dd] *= alpha;
            #pragma unroll
            for (int j = 0; j < 4; j++) Ps[(ty * 4 + i) * 65 + tx * 4 + j] = sc[i][j];
        }
        __syncthreads();

        for (int j = 0; j < 64; j++) {
            float vv[8];
            #pragma unroll
            for (int dd = 0; dd < 8; dd++) vv[dd] = Vs[j * 128 + tx * 8 + dd];
            #pragma unroll
            for (int i = 0; i < 4; i++) {
                float p = Ps[(ty * 4 + i) * 65 + j];
                #pragma unroll
                for (int dd = 0; dd < 8; dd++) acc[i][dd] = fmaf(p, vv[dd], acc[i][dd]);
            }
        }
    }

    #pragma unroll
    for (int i = 0; i < 4; i++) {
        int srow = qb * 64 + ty * 4 + i;
        float invl = 1.f / l[i];
        size_t base = (((size_t)(b * S_ + srow)) * NH_ + h) * DH_ + tx * 8;
        #pragma unroll
        for (int dd = 0; dd < 8; dd++) o[base + dd] = to_tf32(acc[i][dd] * invl);
    }
}

// ---------------- silu(gate) * up from fused gu buffer, tf32 output ----------------
__global__ void silu_mul_kernel(const float* __restrict__ gu, float* __restrict__ out, long total4) {
    long i = (long)blockIdx.x * blockDim.x + threadIdx.x;
    if (i >= total4) return;
    long mrow = i >> 11;             // / 2048 float4 per out row
    int c4 = (int)(i & 2047);
    const float4* gu4 = (const float4*)gu;
    float4 gv = gu4[mrow * 4096 + c4];
    float4 uv = gu4[mrow * 4096 + 2048 + c4];
    float4 o;
    o.x = to_tf32(gv.x / (1.f + __expf(-gv.x)) * uv.x);
    o.y = to_tf32(gv.y / (1.f + __expf(-gv.y)) * uv.y);
    o.z = to_tf32(gv.z / (1.f + __expf(-gv.z)) * uv.z);
    o.w = to_tf32(gv.w / (1.f + __expf(-gv.w)) * uv.w);
    ((float4*)out)[i] = o;
}

// ---------------- launch ----------------
static inline void launch_cvt(const float* src, float* dst, int ncols4, int stride4, int off4, long total4) {
    int blocks = (int)((total4 + 255) / 256);
    cvt2d_kernel<<<blocks, 256>>>(src, dst, ncols4, stride4, off4, total4);
}

extern "C" void kernel_launch(void* const* d_in, const int* in_sizes, int n_in,
                              void* d_out, int out_size) {
    const float* hidden = (const float*)d_in[0];
    const float* cosp   = (const float*)d_in[1];
    const float* sinp   = (const float*)d_in[2];
    const float* wq     = (const float*)d_in[3];
    const float* wk     = (const float*)d_in[4];
    const float* wv     = (const float*)d_in[5];
    const float* wo     = (const float*)d_in[6];
    const float* qnw    = (const float*)d_in[7];
    const float* knw    = (const float*)d_in[8];
    const float* anw    = (const float*)d_in[9];
    const float* mnw    = (const float*)d_in[10];
    const float* wgate  = (const float*)d_in[11];
    const float* wup    = (const float*)d_in[12];
    const float* wdown  = (const float*)d_in[13];
    float* out = (float*)d_out;

    float *xnorm, *qkv, *attn, *h1, *x2, *gu, *act;
    float *Wqkv, *Wo, *Wgu, *Wdn;
    cudaGetSymbolAddress((void**)&xnorm, g_xnorm);
    cudaGetSymbolAddress((void**)&qkv, g_qkv);
    cudaGetSymbolAddress((void**)&attn, g_attn);
    cudaGetSymbolAddress((void**)&h1, g_h1);
    cudaGetSymbolAddress((void**)&x2, g_x2);
    cudaGetSymbolAddress((void**)&gu, g_gu);
    cudaGetSymbolAddress((void**)&act, g_act);
    cudaGetSymbolAddress((void**)&Wqkv, w_qkv);
    cudaGetSymbolAddress((void**)&Wo, w_o);
    cudaGetSymbolAddress((void**)&Wgu, w_gu);
    cudaGetSymbolAddress((void**)&Wdn, w_dn);

    const int attn_smem = ATTN_SMEM_FLOATS * sizeof(float);
    cudaFuncSetAttribute(attn_kernel, cudaFuncAttributeMaxDynamicSharedMemorySize, attn_smem);
    const int gemm_smem = 2 * G_STAGE * sizeof(float);
    cudaFuncSetAttribute(gemm_tf32, cudaFuncAttributeMaxDynamicSharedMemorySize, gemm_smem);

    // 0) convert weights to tf32 (fused/concatenated layouts)
    launch_cvt(wq,    Wqkv, 512,  768,  0,    (long)H_ * 512);        // [2048 x 2048] -> cols 0..2047
    launch_cvt(wk,    Wqkv, 128,  768,  512,  (long)H_ * 128);        // -> cols 2048..2559
    launch_cvt(wv,    Wqkv, 128,  768,  640,  (long)H_ * 128);        // -> cols 2560..3071
    launch_cvt(wo,    Wo,   512,  512,  0,    (long)H_ * 512);
    launch_cvt(wgate, Wgu,  2048, 4096, 0,    (long)H_ * 2048);       // -> cols 0..8191
    launch_cvt(wup,   Wgu,  2048, 4096, 2048, (long)H_ * 2048);       // -> cols 8192..16383
    launch_cvt(wdown, Wdn,  512,  512,  0,    (long)I_ * 512);

    // 1) attn rmsnorm (tf32 out)
    rmsnorm_kernel<<<M_, 256>>>(hidden, anw, xnorm, H_);

    // 2) fused QKV projection
    gemm_tf32<<<dim3(QKV_N_ / 128, M_ / 128), 128, gemm_smem>>>(xnorm, Wqkv, nullptr, qkv, M_, QKV_N_, H_);

    // 3) q/k norm + rope (in place in qkv buffer)
    qknorm_rope_kernel<<<M_ * NH_, DH_>>>(qkv, QKV_N_, qnw, cosp, sinp, NH_);
    qknorm_rope_kernel<<<M_ * NKV_, DH_>>>(qkv + 2048, QKV_N_, knw, cosp, sinp, NKV_);

    // 4) attention (tf32 out)
    attn_kernel<<<dim3(S_ / 64, NH_, B_), 256, attn_smem>>>(qkv, attn);

    // 5) O projection + residual
    gemm_tf32<<<dim3(H_ / 128, M_ / 128), 128, gemm_smem>>>(attn, Wo, hidden, h1, M_, H_, H_);

    // 6) mlp rmsnorm (tf32 out)
    rmsnorm_kernel<<<M_, 256>>>(h1, mnw, x2, H_);

    // 7) fused gate+up projection
    gemm_tf32<<<dim3(GU_N_ / 128, M_ / 128), 128, gemm_smem>>>(x2, Wgu, nullptr, gu, M_, GU_N_, H_);

    // 8) silu * up (tf32 out)
    {
        long total4 = (long)M_ * I_ / 4;
        int blocks = (int)((total4 + 255) / 256);
        silu_mul_kernel<<<blocks, 256>>>(gu, act, total4);
    }

    // 9) down projection + residual -> output
    gemm_tf32<<<dim3(H_ / 128, M_ / 128), 128, gemm_smem>>>(act, Wdn, h1, out, M_, H_, I_);
}